// round 7
// baseline (speedup 1.0000x reference)
#include <cuda_runtime.h>
#include <cuda_bf16.h>
#include <cuda_fp16.h>
#include <cstdint>

#define TOTAL 6464
#define TPAD  6656
#define HEADS 8
#define BATCH 8
#define NPERS 296

// ---------------- scratch ----------------------------------------------------
__device__ uint32_t g_q16[TPAD * 128];   // fp16x2 [token][128], Q scaled by sc*log2e
__device__ uint32_t g_k16[TPAD * 128];
__device__ uint32_t g_v16[TPAD * 128];   // V row-major fp16x2
__device__ __nv_bfloat16 g_xh[TPAD * 256], g_xl[TPAD * 256];
__device__ __nv_bfloat16 g_ah[TPAD * 256], g_al[TPAD * 256];
__device__ __nv_bfloat16 g_wqh[768 * 256], g_wql[768 * 256];
__device__ __nv_bfloat16 g_wph[256 * 256], g_wpl[256 * 256];
__device__ int g_off[BATCH + 1];
__device__ int g_pairs[64];
__device__ int g_nwork;
__device__ int g_ticket;

// ---------------- helpers ----------------------------------------------------
__device__ __forceinline__ uint32_t packbf(float x, float y) {
    __nv_bfloat162 t = __floats2bfloat162_rn(x, y);
    return reinterpret_cast<uint32_t&>(t);
}
__device__ __forceinline__ uint32_t packh2(float x, float y) {
    __half2 t = __floats2half2_rn(x, y);
    return reinterpret_cast<uint32_t&>(t);
}
__device__ __forceinline__ float bfhi(float x) {
    return __bfloat162float(__float2bfloat16(x));
}
__device__ __forceinline__ uint32_t ex2h2(uint32_t x) {
    uint32_t y; asm("ex2.approx.f16x2 %0, %1;" : "=r"(y) : "r"(x)); return y;
}
__device__ __forceinline__ void mma_bf16(float* c, const uint32_t* a, const uint32_t* b) {
    asm("mma.sync.aligned.m16n8k16.row.col.f32.bf16.bf16.f32 "
        "{%0,%1,%2,%3},{%4,%5,%6,%7},{%8,%9},{%0,%1,%2,%3};"
        : "+f"(c[0]), "+f"(c[1]), "+f"(c[2]), "+f"(c[3])
        : "r"(a[0]), "r"(a[1]), "r"(a[2]), "r"(a[3]), "r"(b[0]), "r"(b[1]));
}
__device__ __forceinline__ void mma_f16(float* c, uint32_t a0, uint32_t a1,
                                        uint32_t a2, uint32_t a3,
                                        uint32_t b0, uint32_t b1) {
    asm("mma.sync.aligned.m16n8k16.row.col.f32.f16.f16.f32 "
        "{%0,%1,%2,%3},{%4,%5,%6,%7},{%8,%9},{%0,%1,%2,%3};"
        : "+f"(c[0]), "+f"(c[1]), "+f"(c[2]), "+f"(c[3])
        : "r"(a0), "r"(a1), "r"(a2), "r"(a3), "r"(b0), "r"(b1));
}
__device__ __forceinline__ void ldm4(uint32_t* d, uint32_t addr) {
    asm volatile("ldmatrix.sync.aligned.m8n8.x4.shared.b16 {%0,%1,%2,%3}, [%4];"
                 : "=r"(d[0]), "=r"(d[1]), "=r"(d[2]), "=r"(d[3]) : "r"(addr));
}
__device__ __forceinline__ void ldm4t(uint32_t* d, uint32_t addr) {
    asm volatile("ldmatrix.sync.aligned.m8n8.x4.trans.shared.b16 {%0,%1,%2,%3}, [%4];"
                 : "=r"(d[0]), "=r"(d[1]), "=r"(d[2]), "=r"(d[3]) : "r"(addr));
}
__device__ __forceinline__ void cpa16(uint32_t dst_smem, const void* src) {
    asm volatile("cp.async.cg.shared.global [%0], [%1], 16;" :: "r"(dst_smem), "l"(src));
}
#define CP_COMMIT asm volatile("cp.async.commit_group;")
#define CP_WAIT1 asm volatile("cp.async.wait_group 1;")
#define CP_WAIT0 asm volatile("cp.async.wait_group 0;")

// ---------------- fused prep: split x, offsets, work list, weight transposes -
__global__ void prep(const float4* __restrict__ x, const int* __restrict__ lens,
                     const float* __restrict__ Wq, const float* __restrict__ Wp)
{
    const int blk = blockIdx.x, tid = threadIdx.x;
    if (blk < 1616) {
        int i = blk * 256 + tid;
        if (i == 0) {
            int s = 0;
            for (int k = 0; k < BATCH; k++) { g_off[k] = s; s += lens[k]; }
            g_off[BATCH] = s;
            int ord[BATCH];
            for (int k = 0; k < BATCH; k++) ord[k] = k;
            for (int a = 1; a < BATCH; a++) {
                int key = ord[a], j = a - 1;
                while (j >= 0 && lens[ord[j]] < lens[key]) { ord[j + 1] = ord[j]; j--; }
                ord[j + 1] = key;
            }
            int n = 0;
            for (int a = 0; a < BATCH; a++) {
                int b = ord[a];
                int nt = (lens[b] + 127) >> 7;
                for (int qt = 0; qt < nt; qt++) g_pairs[n++] = (b << 8) | qt;
            }
            g_nwork = n * HEADS;
            g_ticket = 0;
        }
        float4 v = x[i];
        uint32_t* H = (uint32_t*)g_xh;
        uint32_t* L = (uint32_t*)g_xl;
        float hx = bfhi(v.x), hy = bfhi(v.y), hz = bfhi(v.z), hw = bfhi(v.w);
        H[2 * i + 0] = packbf(v.x, v.y);
        H[2 * i + 1] = packbf(v.z, v.w);
        L[2 * i + 0] = packbf(v.x - hx, v.y - hy);
        L[2 * i + 1] = packbf(v.z - hz, v.w - hw);
        return;
    }
    const float* W; __nv_bfloat16 *OH, *OL; int N, n0, k0;
    if (blk < 1808) {
        int idx = blk - 1616;
        W = Wq; OH = g_wqh; OL = g_wql; N = 768;
        n0 = (idx % 24) * 32; k0 = (idx / 24) * 32;
    } else {
        int idx = blk - 1808;
        W = Wp; OH = g_wph; OL = g_wpl; N = 256;
        n0 = (idx % 8) * 32; k0 = (idx / 8) * 32;
    }
    __shared__ float t[32][33];
    int tx = tid & 31, ty = tid >> 5;
    #pragma unroll
    for (int j = 0; j < 4; j++)
        t[ty + 8 * j][tx] = W[(size_t)(k0 + ty + 8 * j) * N + n0 + tx];
    __syncthreads();
    #pragma unroll
    for (int j = 0; j < 4; j++) {
        float v = t[tx][ty + 8 * j];
        int n = n0 + ty + 8 * j, k = k0 + tx;
        float h = bfhi(v);
        OH[(size_t)n * 256 + k] = __float2bfloat16(v);
        OL[(size_t)n * 256 + k] = __float2bfloat16(v - h);
    }
}

// ---------------------------------------------------------------------------
// GEMM: C = A @ B^T + bias, split-bf16 3-pass, 3-stage cp.async pipeline,
// single barrier per K-iter. Tile 128x64, BK=32, 256 thr.
// Stage layout (30720B each): AsH[128][20] | AsL | BsH[64][20] | BsL
// ---------------------------------------------------------------------------
__global__ __launch_bounds__(256, 2) void gemm7(
    const __nv_bfloat16* __restrict__ Ah, const __nv_bfloat16* __restrict__ Al,
    const __nv_bfloat16* __restrict__ Bh, const __nv_bfloat16* __restrict__ Bl,
    const float* __restrict__ bias, float* __restrict__ out, int mode)
{
    extern __shared__ uint32_t sm[];

    const int tid = threadIdx.x, lane = tid & 31, wid = tid >> 5;
    const int g = lane >> 2, tig = lane & 3;
    const int wm = (wid >> 1) * 32, wn = (wid & 1) * 32;
    const int row0 = blockIdx.y * 128, col0 = blockIdx.x * 64;
    const int r8 = lane & 7, msel = lane >> 3;

    const uint32_t sbase = (uint32_t)__cvta_generic_to_shared(sm);
    const uint32_t offA = (uint32_t)(((msel & 1) * 8 + r8) * 80 + (msel >> 1) * 16);
    const uint32_t offB = (uint32_t)((msel >> 1) * 640 + r8 * 80 + (msel & 1) * 16);

    const int ra = tid >> 2, sa = tid & 3;
    const uint32_t raoff = (uint32_t)(ra * 80 + sa * 16);
    const __nv_bfloat16* pAh = Ah + (size_t)(row0 + ra) * 256 + sa * 8;
    const __nv_bfloat16* pAl = Al + (size_t)(row0 + ra) * 256 + sa * 8;
    const __nv_bfloat16* pAh2 = pAh + 64 * 256;
    const __nv_bfloat16* pAl2 = pAl + 64 * 256;
    const __nv_bfloat16* pBh = Bh + (size_t)(col0 + ra) * 256 + sa * 8;
    const __nv_bfloat16* pBl = Bl + (size_t)(col0 + ra) * 256 + sa * 8;

    float chi[2][4][4] = {};
    float clo[2][4][4] = {};

#define GSTAGE(s) do {                                                     \
        uint32_t b_ = sbase + (uint32_t)(s) * 30720u;                      \
        cpa16(b_ + raoff, pAh);           cpa16(b_ + 5120 + raoff, pAh2);  \
        cpa16(b_ + 10240 + raoff, pAl);   cpa16(b_ + 15360 + raoff, pAl2); \
        cpa16(b_ + 20480 + raoff, pBh);   cpa16(b_ + 25600 + raoff, pBl);  \
        CP_COMMIT;                                                         \
        pAh += 32; pAh2 += 32; pAl += 32; pAl2 += 32; pBh += 32; pBl += 32;\
    } while (0)

    GSTAGE(0);
    GSTAGE(1);

    #pragma unroll
    for (int it = 0; it < 8; it++) {
        if (it < 6) { CP_WAIT1; } else { CP_WAIT0; }
        __syncthreads();
        if (it < 6) GSTAGE((it + 2) % 3);

        const uint32_t aBufH = sbase + (uint32_t)(it % 3) * 30720u;
        const uint32_t aBufL = aBufH + 10240;
        const uint32_t bBufH = aBufH + 20480;
        const uint32_t bBufL = aBufH + 25600;

        #pragma unroll
        for (int ks = 0; ks < 2; ks++) {
            uint32_t ah[2][4], al[2][4], bh[2][4], bl[2][4];
            #pragma unroll
            for (int mt = 0; mt < 2; mt++) {
                uint32_t ao = (uint32_t)((wm + mt * 16) * 80 + ks * 32) + offA;
                ldm4(ah[mt], aBufH + ao);
                ldm4(al[mt], aBufL + ao);
            }
            #pragma unroll
            for (int p = 0; p < 2; p++) {
                uint32_t bo = (uint32_t)(wn * 80 + p * 1280 + ks * 32) + offB;
                ldm4(bh[p], bBufH + bo);
                ldm4(bl[p], bBufL + bo);
            }
            #pragma unroll
            for (int mt = 0; mt < 2; mt++)
                #pragma unroll
                for (int nt = 0; nt < 4; nt++) {
                    const uint32_t* bhp = &bh[nt >> 1][(nt & 1) * 2];
                    const uint32_t* blp = &bl[nt >> 1][(nt & 1) * 2];
                    mma_bf16(chi[mt][nt], ah[mt], bhp);
                    mma_bf16(clo[mt][nt], ah[mt], blp);
                    mma_bf16(clo[mt][nt], al[mt], bhp);
                }
        }
    }
#undef GSTAGE

    const float sc = 0.17677669529663687f * 1.4426950408889634f;
    #pragma unroll
    for (int mt = 0; mt < 2; mt++)
        #pragma unroll
        for (int nt = 0; nt < 4; nt++) {
            int r = row0 + wm + mt * 16 + g;
            int j = col0 + wn + nt * 8 + 2 * tig;
            float2 bv = *(const float2*)&bias[j];
            float v0 = chi[mt][nt][0] + clo[mt][nt][0] + bv.x;
            float v1 = chi[mt][nt][1] + clo[mt][nt][1] + bv.y;
            float v2 = chi[mt][nt][2] + clo[mt][nt][2] + bv.x;
            float v3 = chi[mt][nt][3] + clo[mt][nt][3] + bv.y;
            if (mode == 0) {
                if (r < TOTAL) { float2 o = {v0, v1};
                    *(float2*)&out[(size_t)r * 256 + j] = o; }
                if (r + 8 < TOTAL) { float2 o = {v2, v3};
                    *(float2*)&out[(size_t)(r + 8) * 256 + j] = o; }
            } else {
                int arr = j >> 8, jc = j & 255;
                uint32_t* dst = (arr == 0) ? g_q16 : (arr == 1) ? g_k16 : g_v16;
                float s = (arr == 0) ? sc : 1.f;
                dst[(size_t)r * 128 + (jc >> 1)] = packh2(v0 * s, v1 * s);
                dst[(size_t)(r + 8) * 128 + (jc >> 1)] = packh2(v2 * s, v3 * s);
            }
        }
}

// ---------------------------------------------------------------------------
// Persistent ragged flash attention: fp16 mma, half2 ex2 softmax, ones-column
// row sums, 3-stage cp.async K/V ring, one barrier per chunk.
// Stage layout (10240B each): Ks[64][20] | Vs[64][20]
// ---------------------------------------------------------------------------
__global__ __launch_bounds__(256, 2) void attn7(const int* __restrict__ lens)
{
    __shared__ __align__(16) uint32_t KV[3][2][64][20];
    __shared__ int s_w;

    const int tid = threadIdx.x, lane = tid & 31, wid = tid >> 5;
    const int g = lane >> 2, tig = lane & 3;
    const int m0 = wid * 16;
    const uint32_t kvbase = (uint32_t)__cvta_generic_to_shared(&KV[0][0][0][0]);
    const uint32_t laneK = (uint32_t)((lane >> 4) * 640 + (lane & 7) * 80 + ((lane >> 3) & 1) * 16);
    const uint32_t laneVt = (uint32_t)(((lane >> 3) & 1) * 640 + (lane & 7) * 80 + (lane >> 4) * 16);
    const int ra = tid >> 2, sa = tid & 3;
    const uint32_t raoff = (uint32_t)(ra * 80 + sa * 16);
    const uint32_t ONE2 = 0x3C003C00u;

    for (;;) {
        if (tid == 0) s_w = atomicAdd(&g_ticket, 1);
        __syncthreads();
        const int w = s_w;
        if (w >= g_nwork) return;
        const int pr = g_pairs[w >> 3], h = w & 7;
        const int b = pr >> 8, qt = pr & 255;
        const int L = lens[b], q0 = qt * 128, off = g_off[b];

        uint32_t qf[2][4];
        {
            size_t rA = (size_t)(off + q0 + m0 + g) * 128;
            size_t rB = rA + 8 * 128;
            #pragma unroll
            for (int ks = 0; ks < 2; ks++) {
                int cb = h * 16 + ks * 8;
                qf[ks][0] = g_q16[rA + cb + tig];
                qf[ks][1] = g_q16[rB + cb + tig];
                qf[ks][2] = g_q16[rA + cb + tig + 4];
                qf[ks][3] = g_q16[rB + cb + tig + 4];
            }
        }

        float o[4][4];
        #pragma unroll
        for (int nt = 0; nt < 4; nt++)
            #pragma unroll
            for (int i = 0; i < 4; i++) o[nt][i] = 0.f;
        float lacc[4] = {0.f, 0.f, 0.f, 0.f};

        const int nch = (L + 63) >> 6;

        const uint32_t* pk = g_k16 + (size_t)(off + ra) * 128 + h * 16 + sa * 4;
        const uint32_t* pv = g_v16 + (size_t)(off + ra) * 128 + h * 16 + sa * 4;

#define ASTAGE(s) do {                                        \
        uint32_t b_ = kvbase + (uint32_t)(s) * 10240u;        \
        cpa16(b_ + raoff, pk);                                \
        cpa16(b_ + 5120 + raoff, pv);                         \
        CP_COMMIT;                                            \
        pk += 8192; pv += 8192;                               \
    } while (0)

        ASTAGE(0);
        if (nch > 1) ASTAGE(1);
        int cur = 0, nxt = 2;

        for (int c = 0; c < nch; c++) {
            if (c + 1 < nch) { CP_WAIT1; } else { CP_WAIT0; }
            __syncthreads();
            if (c + 2 < nch) { ASTAGE(nxt); if (++nxt == 3) nxt = 0; }

            const uint32_t kb = kvbase + (uint32_t)cur * 10240u;
            const uint32_t vb = kb + 5120u;
            if (++cur == 3) cur = 0;
            const int k0 = c * 64;

            // S = Q @ K^T (log2 domain)
            float s_[8][4] = {};
            #pragma unroll
            for (int ks = 0; ks < 2; ks++) {
                #pragma unroll
                for (int p = 0; p < 4; p++) {
                    uint32_t kr[4];
                    ldm4(kr, kb + p * 1280 + ks * 32 + laneK);
                    mma_f16(s_[2 * p], qf[ks][0], qf[ks][1], qf[ks][2], qf[ks][3],
                            kr[0], kr[1]);
                    mma_f16(s_[2 * p + 1], qf[ks][0], qf[ks][1], qf[ks][2], qf[ks][3],
                            kr[2], kr[3]);
                }
            }
            if (k0 + 64 > L) {
                #pragma unroll
                for (int jt = 0; jt < 8; jt++) {
                    int col = k0 + jt * 8 + 2 * tig;
                    if (col >= L)     { s_[jt][0] = -1e9f; s_[jt][2] = -1e9f; }
                    if (col + 1 >= L) { s_[jt][1] = -1e9f; s_[jt][3] = -1e9f; }
                }
            }

            // P = exp2(S) in half2 + PV mma + ones-column row sums
            #pragma unroll
            for (int t = 0; t < 4; t++) {
                uint32_t a0 = ex2h2(packh2(s_[2 * t][0],     s_[2 * t][1]));
                uint32_t a1 = ex2h2(packh2(s_[2 * t][2],     s_[2 * t][3]));
                uint32_t a2 = ex2h2(packh2(s_[2 * t + 1][0], s_[2 * t + 1][1]));
                uint32_t a3 = ex2h2(packh2(s_[2 * t + 1][2], s_[2 * t + 1][3]));
                uint32_t v0[4], v1[4];
                ldm4t(v0, vb + t * 1280 + laneVt);
                ldm4t(v1, vb + t * 1280 + 32 + laneVt);
                mma_f16(o[0], a0, a1, a2, a3, v0[0], v0[1]);
                mma_f16(o[1], a0, a1, a2, a3, v0[2], v0[3]);
                mma_f16(o[2], a0, a1, a2, a3, v1[0], v1[1]);
                mma_f16(o[3], a0, a1, a2, a3, v1[2], v1[3]);
                mma_f16(lacc, a0, a1, a2, a3, ONE2, ONE2);
            }
        }
#undef ASTAGE

        float i0 = 1.f / lacc[0], i1 = 1.f / lacc[2];

        int qa = q0 + m0 + g, qb = qa + 8;
        uint32_t* AH = (uint32_t*)g_ah;
        uint32_t* AL = (uint32_t*)g_al;
        #pragma unroll
        for (int nt = 0; nt < 4; nt++) {
            int ci = h * 16 + nt * 4 + tig;
            if (qa < L) {
                float v0 = o[nt][0] * i0, v1 = o[nt][1] * i0;
                float h0 = bfhi(v0), h1 = bfhi(v1);
                AH[(size_t)(off + qa) * 128 + ci] = packbf(v0, v1);
                AL[(size_t)(off + qa) * 128 + ci] = packbf(v0 - h0, v1 - h1);
            }
            if (qb < L) {
                float v2 = o[nt][2] * i1, v3 = o[nt][3] * i1;
                float h2 = bfhi(v2), h3 = bfhi(v3);
                AH[(size_t)(off + qb) * 128 + ci] = packbf(v2, v3);
                AL[(size_t)(off + qb) * 128 + ci] = packbf(v2 - h2, v3 - h3);
            }
        }
    }
}

// ---------------------------------------------------------------------------
extern "C" void kernel_launch(void* const* d_in, const int* in_sizes, int n_in,
                              void* d_out, int out_size)
{
    const float* x      = (const float*)d_in[0];
    const int*   lens   = (const int*)d_in[2];
    const float* qkv_w  = (const float*)d_in[3];
    const float* qkv_b  = (const float*)d_in[4];
    const float* proj_w = (const float*)d_in[5];
    const float* proj_b = (const float*)d_in[6];
    float* out = (float*)d_out;

    __nv_bfloat16 *xh, *xl, *ah, *al, *wqh, *wql, *wph, *wpl;
    cudaGetSymbolAddress((void**)&xh,  g_xh);
    cudaGetSymbolAddress((void**)&xl,  g_xl);
    cudaGetSymbolAddress((void**)&ah,  g_ah);
    cudaGetSymbolAddress((void**)&al,  g_al);
    cudaGetSymbolAddress((void**)&wqh, g_wqh);
    cudaGetSymbolAddress((void**)&wql, g_wql);
    cudaGetSymbolAddress((void**)&wph, g_wph);
    cudaGetSymbolAddress((void**)&wpl, g_wpl);

    cudaFuncSetAttribute(gemm7, cudaFuncAttributeMaxDynamicSharedMemorySize, 92160);

    prep<<<1872, 256>>>((const float4*)x, lens, qkv_w, proj_w);
    gemm7<<<dim3(12, 51), 256, 92160>>>(xh, xl, wqh, wql, qkv_b, nullptr, 1);
    attn7<<<NPERS, 256>>>(lens);
    gemm7<<<dim3(4, 51), 256, 92160>>>(ah, al, wph, wpl, proj_b, out, 0);
}

// round 8
// speedup vs baseline: 1.3908x; 1.3908x over previous
#include <cuda_runtime.h>
#include <cuda_fp16.h>
#include <cstdint>

#define TOTAL 6464
#define TPAD  6656
#define HEADS 8
#define BATCH 8
#define NPERS 296

// ---------------- scratch ----------------------------------------------------
__device__ uint32_t g_x16[TPAD * 128];   // input x, fp16x2 [token][128]
__device__ uint32_t g_q16[TPAD * 128];   // Q fp16x2, pre-scaled by sc*log2e
__device__ uint32_t g_k16[TPAD * 128];
__device__ uint32_t g_v16[TPAD * 128];
__device__ uint32_t g_a16[TPAD * 128];   // attention output fp16x2
__device__ __half g_wq16[768 * 256];     // qkv_w^T  [n][k] fp16
__device__ __half g_wp16[256 * 256];     // proj_w^T [n][k] fp16
__device__ int g_off[BATCH + 1];
__device__ int g_pairs[64];
__device__ int g_nwork;
__device__ int g_ticket;

// ---------------- helpers ----------------------------------------------------
__device__ __forceinline__ uint32_t packh2(float x, float y) {
    __half2 t = __floats2half2_rn(x, y);
    return reinterpret_cast<uint32_t&>(t);
}
__device__ __forceinline__ uint32_t ex2h2(uint32_t x) {
    uint32_t y; asm("ex2.approx.f16x2 %0, %1;" : "=r"(y) : "r"(x)); return y;
}
__device__ __forceinline__ void mma_f16(float* c, uint32_t a0, uint32_t a1,
                                        uint32_t a2, uint32_t a3,
                                        uint32_t b0, uint32_t b1) {
    asm("mma.sync.aligned.m16n8k16.row.col.f32.f16.f16.f32 "
        "{%0,%1,%2,%3},{%4,%5,%6,%7},{%8,%9},{%0,%1,%2,%3};"
        : "+f"(c[0]), "+f"(c[1]), "+f"(c[2]), "+f"(c[3])
        : "r"(a0), "r"(a1), "r"(a2), "r"(a3), "r"(b0), "r"(b1));
}
__device__ __forceinline__ void ldm4(uint32_t* d, uint32_t addr) {
    asm volatile("ldmatrix.sync.aligned.m8n8.x4.shared.b16 {%0,%1,%2,%3}, [%4];"
                 : "=r"(d[0]), "=r"(d[1]), "=r"(d[2]), "=r"(d[3]) : "r"(addr));
}
__device__ __forceinline__ void ldm4t(uint32_t* d, uint32_t addr) {
    asm volatile("ldmatrix.sync.aligned.m8n8.x4.trans.shared.b16 {%0,%1,%2,%3}, [%4];"
                 : "=r"(d[0]), "=r"(d[1]), "=r"(d[2]), "=r"(d[3]) : "r"(addr));
}
__device__ __forceinline__ void cpa16(uint32_t dst_smem, const void* src) {
    asm volatile("cp.async.cg.shared.global [%0], [%1], 16;" :: "r"(dst_smem), "l"(src));
}
#define CP_COMMIT asm volatile("cp.async.commit_group;")
#define CP_WAIT1 asm volatile("cp.async.wait_group 1;")
#define CP_WAIT0 asm volatile("cp.async.wait_group 0;")

// ---------------- fused prep: x->fp16, offsets, work list, weight transposes -
__global__ void prep(const float4* __restrict__ x, const int* __restrict__ lens,
                     const float* __restrict__ Wq, const float* __restrict__ Wp)
{
    const int blk = blockIdx.x, tid = threadIdx.x;
    if (blk < 1616) {
        int i = blk * 256 + tid;
        if (i == 0) {
            int s = 0;
            for (int k = 0; k < BATCH; k++) { g_off[k] = s; s += lens[k]; }
            g_off[BATCH] = s;
            int ord[BATCH];
            for (int k = 0; k < BATCH; k++) ord[k] = k;
            for (int a = 1; a < BATCH; a++) {
                int key = ord[a], j = a - 1;
                while (j >= 0 && lens[ord[j]] < lens[key]) { ord[j + 1] = ord[j]; j--; }
                ord[j + 1] = key;
            }
            int n = 0;
            for (int a = 0; a < BATCH; a++) {
                int b = ord[a];
                int nt = (lens[b] + 127) >> 7;
                for (int qt = 0; qt < nt; qt++) g_pairs[n++] = (b << 8) | qt;
            }
            g_nwork = n * HEADS;
            g_ticket = 0;
        }
        float4 v = x[i];
        g_x16[2 * i + 0] = packh2(v.x, v.y);
        g_x16[2 * i + 1] = packh2(v.z, v.w);
        return;
    }
    const float* W; __half* O; int N, n0, k0;
    if (blk < 1808) {
        int idx = blk - 1616;
        W = Wq; O = g_wq16; N = 768;
        n0 = (idx % 24) * 32; k0 = (idx / 24) * 32;
    } else {
        int idx = blk - 1808;
        W = Wp; O = g_wp16; N = 256;
        n0 = (idx % 8) * 32; k0 = (idx / 8) * 32;
    }
    __shared__ float t[32][33];
    int tx = tid & 31, ty = tid >> 5;
    #pragma unroll
    for (int j = 0; j < 4; j++)
        t[ty + 8 * j][tx] = W[(size_t)(k0 + ty + 8 * j) * N + n0 + tx];
    __syncthreads();
    #pragma unroll
    for (int j = 0; j < 4; j++) {
        float v = t[tx][ty + 8 * j];
        int n = n0 + ty + 8 * j, k = k0 + tx;
        O[(size_t)n * 256 + k] = __float2half(v);
    }
}

// ---------------------------------------------------------------------------
// Single-pass fp16 GEMM: C = A @ B^T + bias. Tile 128x64, BK=32, 256 thr,
// 3-stage cp.async ring (15360B/stage: A[128][20]u32 | B[64][20]u32).
// mode 0: fp32 out (guard r<TOTAL). mode 1: QKV epilogue -> g_q16/g_k16/g_v16.
// ---------------------------------------------------------------------------
__global__ __launch_bounds__(256, 3) void gemm8(
    const __half* __restrict__ A, const __half* __restrict__ B,
    const float* __restrict__ bias, float* __restrict__ out, int mode)
{
    extern __shared__ uint32_t sm[];

    const int tid = threadIdx.x, lane = tid & 31, wid = tid >> 5;
    const int g = lane >> 2, tig = lane & 3;
    const int wm = (wid >> 1) * 32, wn = (wid & 1) * 32;
    const int row0 = blockIdx.y * 128, col0 = blockIdx.x * 64;
    const int r8 = lane & 7, msel = lane >> 3;

    const uint32_t sbase = (uint32_t)__cvta_generic_to_shared(sm);
    const uint32_t offA = (uint32_t)(((msel & 1) * 8 + r8) * 80 + (msel >> 1) * 16);
    const uint32_t offB = (uint32_t)((msel >> 1) * 640 + r8 * 80 + (msel & 1) * 16);

    const int ra = tid >> 2, sa = tid & 3;
    const uint32_t raoff = (uint32_t)(ra * 80 + sa * 16);
    const __half* pA  = A + (size_t)(row0 + ra) * 256 + sa * 8;
    const __half* pA2 = pA + 64 * 256;
    const __half* pB  = B + (size_t)(col0 + ra) * 256 + sa * 8;

    float c[2][4][4] = {};

#define GSTAGE(s) do {                                       \
        uint32_t b_ = sbase + (uint32_t)(s) * 15360u;        \
        cpa16(b_ + raoff, pA);                               \
        cpa16(b_ + 5120 + raoff, pA2);                       \
        cpa16(b_ + 10240 + raoff, pB);                       \
        CP_COMMIT;                                           \
        pA += 32; pA2 += 32; pB += 32;                       \
    } while (0)

    GSTAGE(0);
    GSTAGE(1);

    #pragma unroll
    for (int it = 0; it < 8; it++) {
        if (it < 6) { CP_WAIT1; } else { CP_WAIT0; }
        __syncthreads();
        if (it < 6) GSTAGE((it + 2) % 3);

        const uint32_t aBuf = sbase + (uint32_t)(it % 3) * 15360u;
        const uint32_t bBuf = aBuf + 10240u;

        #pragma unroll
        for (int ks = 0; ks < 2; ks++) {
            uint32_t a[2][4], b[2][4];
            #pragma unroll
            for (int mt = 0; mt < 2; mt++)
                ldm4(a[mt], aBuf + (uint32_t)((wm + mt * 16) * 80 + ks * 32) + offA);
            #pragma unroll
            for (int p = 0; p < 2; p++)
                ldm4(b[p], bBuf + (uint32_t)(wn * 80 + p * 1280 + ks * 32) + offB);
            #pragma unroll
            for (int mt = 0; mt < 2; mt++)
                #pragma unroll
                for (int nt = 0; nt < 4; nt++) {
                    const uint32_t* bp = &b[nt >> 1][(nt & 1) * 2];
                    mma_f16(c[mt][nt], a[mt][0], a[mt][1], a[mt][2], a[mt][3],
                            bp[0], bp[1]);
                }
        }
    }
#undef GSTAGE

    const float sc = 0.17677669529663687f * 1.4426950408889634f;  // hd^-0.5 * log2(e)
    #pragma unroll
    for (int mt = 0; mt < 2; mt++)
        #pragma unroll
        for (int nt = 0; nt < 4; nt++) {
            int r = row0 + wm + mt * 16 + g;
            int j = col0 + wn + nt * 8 + 2 * tig;
            float2 bv = *(const float2*)&bias[j];
            float v0 = c[mt][nt][0] + bv.x, v1 = c[mt][nt][1] + bv.y;
            float v2 = c[mt][nt][2] + bv.x, v3 = c[mt][nt][3] + bv.y;
            if (mode == 0) {
                if (r < TOTAL) { float2 o = {v0, v1};
                    *(float2*)&out[(size_t)r * 256 + j] = o; }
                if (r + 8 < TOTAL) { float2 o = {v2, v3};
                    *(float2*)&out[(size_t)(r + 8) * 256 + j] = o; }
            } else {
                int arr = j >> 8, jc = j & 255;
                uint32_t* dst = (arr == 0) ? g_q16 : (arr == 1) ? g_k16 : g_v16;
                float s = (arr == 0) ? sc : 1.f;
                dst[(size_t)r * 128 + (jc >> 1)] = packh2(v0 * s, v1 * s);
                dst[(size_t)(r + 8) * 128 + (jc >> 1)] = packh2(v2 * s, v3 * s);
            }
        }
}

// ---------------------------------------------------------------------------
// Persistent ragged flash attention: fp16 mma, half2 ex2 softmax, ones-column
// row sums, 3-stage cp.async K/V ring, one barrier per chunk.
// ---------------------------------------------------------------------------
__global__ __launch_bounds__(256, 2) void attn8(const int* __restrict__ lens)
{
    __shared__ __align__(16) uint32_t KV[3][2][64][20];
    __shared__ int s_w;

    const int tid = threadIdx.x, lane = tid & 31, wid = tid >> 5;
    const int g = lane >> 2, tig = lane & 3;
    const int m0 = wid * 16;
    const uint32_t kvbase = (uint32_t)__cvta_generic_to_shared(&KV[0][0][0][0]);
    const uint32_t laneK = (uint32_t)((lane >> 4) * 640 + (lane & 7) * 80 + ((lane >> 3) & 1) * 16);
    const uint32_t laneVt = (uint32_t)(((lane >> 3) & 1) * 640 + (lane & 7) * 80 + (lane >> 4) * 16);
    const int ra = tid >> 2, sa = tid & 3;
    const uint32_t raoff = (uint32_t)(ra * 80 + sa * 16);
    const uint32_t ONE2 = 0x3C003C00u;

    for (;;) {
        if (tid == 0) s_w = atomicAdd(&g_ticket, 1);
        __syncthreads();
        const int w = s_w;
        if (w >= g_nwork) return;
        const int pr = g_pairs[w >> 3], h = w & 7;
        const int b = pr >> 8, qt = pr & 255;
        const int L = lens[b], q0 = qt * 128, off = g_off[b];

        uint32_t qf[2][4];
        {
            size_t rA = (size_t)(off + q0 + m0 + g) * 128;
            size_t rB = rA + 8 * 128;
            #pragma unroll
            for (int ks = 0; ks < 2; ks++) {
                int cb = h * 16 + ks * 8;
                qf[ks][0] = g_q16[rA + cb + tig];
                qf[ks][1] = g_q16[rB + cb + tig];
                qf[ks][2] = g_q16[rA + cb + tig + 4];
                qf[ks][3] = g_q16[rB + cb + tig + 4];
            }
        }

        float o[4][4];
        #pragma unroll
        for (int nt = 0; nt < 4; nt++)
            #pragma unroll
            for (int i = 0; i < 4; i++) o[nt][i] = 0.f;
        float lacc[4] = {0.f, 0.f, 0.f, 0.f};

        const int nch = (L + 63) >> 6;

        const uint32_t* pk = g_k16 + (size_t)(off + ra) * 128 + h * 16 + sa * 4;
        const uint32_t* pv = g_v16 + (size_t)(off + ra) * 128 + h * 16 + sa * 4;

#define ASTAGE(s) do {                                        \
        uint32_t b_ = kvbase + (uint32_t)(s) * 10240u;        \
        cpa16(b_ + raoff, pk);                                \
        cpa16(b_ + 5120 + raoff, pv);                         \
        CP_COMMIT;                                            \
        pk += 8192; pv += 8192;                               \
    } while (0)

        ASTAGE(0);
        if (nch > 1) ASTAGE(1);
        int cur = 0, nxt = 2;

        for (int c = 0; c < nch; c++) {
            if (c + 1 < nch) { CP_WAIT1; } else { CP_WAIT0; }
            __syncthreads();
            if (c + 2 < nch) { ASTAGE(nxt); if (++nxt == 3) nxt = 0; }

            const uint32_t kb = kvbase + (uint32_t)cur * 10240u;
            const uint32_t vb = kb + 5120u;
            if (++cur == 3) cur = 0;
            const int k0 = c * 64;

            float s_[8][4] = {};
            #pragma unroll
            for (int ks = 0; ks < 2; ks++) {
                #pragma unroll
                for (int p = 0; p < 4; p++) {
                    uint32_t kr[4];
                    ldm4(kr, kb + p * 1280 + ks * 32 + laneK);
                    mma_f16(s_[2 * p], qf[ks][0], qf[ks][1], qf[ks][2], qf[ks][3],
                            kr[0], kr[1]);
                    mma_f16(s_[2 * p + 1], qf[ks][0], qf[ks][1], qf[ks][2], qf[ks][3],
                            kr[2], kr[3]);
                }
            }
            if (k0 + 64 > L) {
                #pragma unroll
                for (int jt = 0; jt < 8; jt++) {
                    int col = k0 + jt * 8 + 2 * tig;
                    if (col >= L)     { s_[jt][0] = -1e9f; s_[jt][2] = -1e9f; }
                    if (col + 1 >= L) { s_[jt][1] = -1e9f; s_[jt][3] = -1e9f; }
                }
            }

            #pragma unroll
            for (int t = 0; t < 4; t++) {
                uint32_t a0 = ex2h2(packh2(s_[2 * t][0],     s_[2 * t][1]));
                uint32_t a1 = ex2h2(packh2(s_[2 * t][2],     s_[2 * t][3]));
                uint32_t a2 = ex2h2(packh2(s_[2 * t + 1][0], s_[2 * t + 1][1]));
                uint32_t a3 = ex2h2(packh2(s_[2 * t + 1][2], s_[2 * t + 1][3]));
                uint32_t v0[4], v1[4];
                ldm4t(v0, vb + t * 1280 + laneVt);
                ldm4t(v1, vb + t * 1280 + 32 + laneVt);
                mma_f16(o[0], a0, a1, a2, a3, v0[0], v0[1]);
                mma_f16(o[1], a0, a1, a2, a3, v0[2], v0[3]);
                mma_f16(o[2], a0, a1, a2, a3, v1[0], v1[1]);
                mma_f16(o[3], a0, a1, a2, a3, v1[2], v1[3]);
                mma_f16(lacc, a0, a1, a2, a3, ONE2, ONE2);
            }
        }
#undef ASTAGE

        float i0 = 1.f / lacc[0], i1 = 1.f / lacc[2];

        int qa = q0 + m0 + g, qb = qa + 8;
        #pragma unroll
        for (int nt = 0; nt < 4; nt++) {
            int ci = h * 16 + nt * 4 + tig;
            if (qa < L)
                g_a16[(size_t)(off + qa) * 128 + ci] = packh2(o[nt][0] * i0, o[nt][1] * i0);
            if (qb < L)
                g_a16[(size_t)(off + qb) * 128 + ci] = packh2(o[nt][2] * i1, o[nt][3] * i1);
        }
    }
}

// ---------------------------------------------------------------------------
extern "C" void kernel_launch(void* const* d_in, const int* in_sizes, int n_in,
                              void* d_out, int out_size)
{
    const float* x      = (const float*)d_in[0];
    const int*   lens   = (const int*)d_in[2];
    const float* qkv_w  = (const float*)d_in[3];
    const float* qkv_b  = (const float*)d_in[4];
    const float* proj_w = (const float*)d_in[5];
    const float* proj_b = (const float*)d_in[6];
    float* out = (float*)d_out;

    __half *x16p, *a16p, *wq, *wp;
    cudaGetSymbolAddress((void**)&x16p, g_x16);
    cudaGetSymbolAddress((void**)&a16p, g_a16);
    cudaGetSymbolAddress((void**)&wq,   g_wq16);
    cudaGetSymbolAddress((void**)&wp,   g_wp16);

    cudaFuncSetAttribute(gemm8, cudaFuncAttributeMaxDynamicSharedMemorySize, 46080);

    prep<<<1872, 256>>>((const float4*)x, lens, qkv_w, proj_w);
    gemm8<<<dim3(12, 51), 256, 46080>>>(x16p, wq, qkv_b, nullptr, 1);
    attn8<<<NPERS, 256>>>(lens);
    gemm8<<<dim3(4, 51), 256, 46080>>>(a16p, wp, proj_b, out, 0);
}

// round 10
// speedup vs baseline: 1.4165x; 1.0185x over previous
#include <cuda_runtime.h>
#include <cuda_fp16.h>
#include <cstdint>

#define TOTAL 6464
#define TPAD  6656
#define HEADS 8
#define BATCH 8
#define NPERS 296

// ---------------- scratch ----------------------------------------------------
__device__ uint32_t g_x16[TPAD * 128];   // input x, fp16x2 [token][128]
__device__ uint32_t g_q16[TPAD * 128];   // Q fp16x2, pre-scaled by sc*log2e
__device__ uint32_t g_k16[TPAD * 128];
__device__ uint32_t g_v16[TPAD * 128];
__device__ uint32_t g_a16[TPAD * 128];   // attention output fp16x2
__device__ __half g_wq16[768 * 256];     // qkv_w^T  [n][k] fp16
__device__ __half g_wp16[256 * 256];     // proj_w^T [n][k] fp16
__device__ int g_off[BATCH + 1];
__device__ int g_pairs[64];
__device__ int g_nwork;
__device__ int g_ticket;

// ---------------- helpers ----------------------------------------------------
__device__ __forceinline__ uint32_t packh2(float x, float y) {
    __half2 t = __floats2half2_rn(x, y);
    return reinterpret_cast<uint32_t&>(t);
}
__device__ __forceinline__ uint32_t ex2h2(uint32_t x) {
    uint32_t y; asm("ex2.approx.f16x2 %0, %1;" : "=r"(y) : "r"(x)); return y;
}
__device__ __forceinline__ void mma_f16(float* c, uint32_t a0, uint32_t a1,
                                        uint32_t a2, uint32_t a3,
                                        uint32_t b0, uint32_t b1) {
    asm("mma.sync.aligned.m16n8k16.row.col.f32.f16.f16.f32 "
        "{%0,%1,%2,%3},{%4,%5,%6,%7},{%8,%9},{%0,%1,%2,%3};"
        : "+f"(c[0]), "+f"(c[1]), "+f"(c[2]), "+f"(c[3])
        : "r"(a0), "r"(a1), "r"(a2), "r"(a3), "r"(b0), "r"(b1));
}
__device__ __forceinline__ void ldm4(uint32_t* d, uint32_t addr) {
    asm volatile("ldmatrix.sync.aligned.m8n8.x4.shared.b16 {%0,%1,%2,%3}, [%4];"
                 : "=r"(d[0]), "=r"(d[1]), "=r"(d[2]), "=r"(d[3]) : "r"(addr));
}
__device__ __forceinline__ void ldm4t(uint32_t* d, uint32_t addr) {
    asm volatile("ldmatrix.sync.aligned.m8n8.x4.trans.shared.b16 {%0,%1,%2,%3}, [%4];"
                 : "=r"(d[0]), "=r"(d[1]), "=r"(d[2]), "=r"(d[3]) : "r"(addr));
}
__device__ __forceinline__ void cpa16(uint32_t dst_smem, const void* src) {
    asm volatile("cp.async.cg.shared.global [%0], [%1], 16;" :: "r"(dst_smem), "l"(src));
}
#define CP_COMMIT asm volatile("cp.async.commit_group;")
#define CP_WAIT1 asm volatile("cp.async.wait_group 1;")
#define CP_WAIT0 asm volatile("cp.async.wait_group 0;")

// ---------------- fused prep: x->fp16, offsets, work list, weight transposes -
__global__ void prep(const float4* __restrict__ x, const int* __restrict__ lens,
                     const float* __restrict__ Wq, const float* __restrict__ Wp)
{
    const int blk = blockIdx.x, tid = threadIdx.x;
    if (blk < 1616) {
        int i = blk * 256 + tid;
        if (i == 0) {
            int s = 0;
            for (int k = 0; k < BATCH; k++) { g_off[k] = s; s += lens[k]; }
            g_off[BATCH] = s;
            int ord[BATCH];
            for (int k = 0; k < BATCH; k++) ord[k] = k;
            for (int a = 1; a < BATCH; a++) {
                int key = ord[a], j = a - 1;
                while (j >= 0 && lens[ord[j]] < lens[key]) { ord[j + 1] = ord[j]; j--; }
                ord[j + 1] = key;
            }
            int n = 0;
            for (int a = 0; a < BATCH; a++) {
                int b = ord[a];
                int nt = (lens[b] + 127) >> 7;
                for (int qt = 0; qt < nt; qt++) g_pairs[n++] = (b << 8) | qt;
            }
            g_nwork = n * HEADS;
            g_ticket = 0;
        }
        float4 v = x[i];
        g_x16[2 * i + 0] = packh2(v.x, v.y);
        g_x16[2 * i + 1] = packh2(v.z, v.w);
        return;
    }
    const float* W; __half* O; int N, n0, k0;
    if (blk < 1808) {
        int idx = blk - 1616;
        W = Wq; O = g_wq16; N = 768;
        n0 = (idx % 24) * 32; k0 = (idx / 24) * 32;
    } else {
        int idx = blk - 1808;
        W = Wp; O = g_wp16; N = 256;
        n0 = (idx % 8) * 32; k0 = (idx / 8) * 32;
    }
    __shared__ float t[32][33];
    int tx = tid & 31, ty = tid >> 5;
    #pragma unroll
    for (int j = 0; j < 4; j++)
        t[ty + 8 * j][tx] = W[(size_t)(k0 + ty + 8 * j) * N + n0 + tx];
    __syncthreads();
    #pragma unroll
    for (int j = 0; j < 4; j++) {
        float v = t[tx][ty + 8 * j];
        int n = n0 + ty + 8 * j, k = k0 + tx;
        O[(size_t)n * 256 + k] = __float2half(v);
    }
}

// ---------------------------------------------------------------------------
// Single-pass fp16 GEMM: C = A @ B^T + bias. Tile 64x64, BK=32, 128 thr
// (4 warps in 2x2, warp tile 32x32), 3-stage cp.async ring
// (10240B/stage: A[64][20]u32 | B[64][20]u32), 6 CTAs/SM.
// mode 0: fp32 out. mode 1: QKV epilogue -> g_q16/g_k16/g_v16.
// ---------------------------------------------------------------------------
__global__ __launch_bounds__(128, 6) void gemm9(
    const __half* __restrict__ A, const __half* __restrict__ B,
    const float* __restrict__ bias, float* __restrict__ out, int mode)
{
    extern __shared__ uint32_t sm[];

    const int tid = threadIdx.x, lane = tid & 31, wid = tid >> 5;
    const int g = lane >> 2, tig = lane & 3;
    const int wm = (wid >> 1) * 32, wn = (wid & 1) * 32;
    const int row0 = blockIdx.y * 64, col0 = blockIdx.x * 64;
    const int r8 = lane & 7, msel = lane >> 3;

    const uint32_t sbase = (uint32_t)__cvta_generic_to_shared(sm);
    const uint32_t offA = (uint32_t)(((msel & 1) * 8 + r8) * 80 + (msel >> 1) * 16);
    const uint32_t offB = (uint32_t)((msel >> 1) * 640 + r8 * 80 + (msel & 1) * 16);

    // staging: 2 A-chunks + 2 B-chunks per thread per stage
    const int ra = tid >> 2, sa = tid & 3;           // ra 0..31, sa 0..3
    const uint32_t d0 = (uint32_t)(ra * 80 + sa * 16);
    const __half* pA  = A + (size_t)(row0 + ra) * 256 + sa * 8;
    const __half* pA2 = pA + 32 * 256;
    const __half* pB  = B + (size_t)(col0 + ra) * 256 + sa * 8;
    const __half* pB2 = pB + 32 * 256;

    float c[2][4][4] = {};

#define GSTAGE(s) do {                                       \
        uint32_t b_ = sbase + (uint32_t)(s) * 10240u;        \
        cpa16(b_ + d0, pA);                                  \
        cpa16(b_ + 2560 + d0, pA2);                          \
        cpa16(b_ + 5120 + d0, pB);                           \
        cpa16(b_ + 7680 + d0, pB2);                          \
        CP_COMMIT;                                           \
        pA += 32; pA2 += 32; pB += 32; pB2 += 32;            \
    } while (0)

    GSTAGE(0);
    GSTAGE(1);

    #pragma unroll
    for (int it = 0; it < 8; it++) {
        if (it < 6) { CP_WAIT1; } else { CP_WAIT0; }
        __syncthreads();
        if (it < 6) GSTAGE((it + 2) % 3);

        const uint32_t aBuf = sbase + (uint32_t)(it % 3) * 10240u;
        const uint32_t bBuf = aBuf + 5120u;

        #pragma unroll
        for (int ks = 0; ks < 2; ks++) {
            uint32_t a[2][4], b[2][4];
            #pragma unroll
            for (int mt = 0; mt < 2; mt++)
                ldm4(a[mt], aBuf + (uint32_t)((wm + mt * 16) * 80 + ks * 32) + offA);
            #pragma unroll
            for (int p = 0; p < 2; p++)
                ldm4(b[p], bBuf + (uint32_t)(wn * 80 + p * 1280 + ks * 32) + offB);
            #pragma unroll
            for (int mt = 0; mt < 2; mt++)
                #pragma unroll
                for (int nt = 0; nt < 4; nt++) {
                    const uint32_t* bp = &b[nt >> 1][(nt & 1) * 2];
                    mma_f16(c[mt][nt], a[mt][0], a[mt][1], a[mt][2], a[mt][3],
                            bp[0], bp[1]);
                }
        }
    }
#undef GSTAGE

    const float sc = 0.17677669529663687f * 1.4426950408889634f;  // hd^-0.5 * log2(e)
    #pragma unroll
    for (int mt = 0; mt < 2; mt++)
        #pragma unroll
        for (int nt = 0; nt < 4; nt++) {
            int r = row0 + wm + mt * 16 + g;                 // M=6464=101*64: no guard
            int j = col0 + wn + nt * 8 + 2 * tig;
            float2 bv = *(const float2*)&bias[j];
            float v0 = c[mt][nt][0] + bv.x, v1 = c[mt][nt][1] + bv.y;
            float v2 = c[mt][nt][2] + bv.x, v3 = c[mt][nt][3] + bv.y;
            if (mode == 0) {
                float2 o0 = {v0, v1};
                *(float2*)&out[(size_t)r * 256 + j] = o0;
                float2 o1 = {v2, v3};
                *(float2*)&out[(size_t)(r + 8) * 256 + j] = o1;
            } else {
                int arr = j >> 8, jc = j & 255;
                uint32_t* dst = (arr == 0) ? g_q16 : (arr == 1) ? g_k16 : g_v16;
                float s = (arr == 0) ? sc : 1.f;
                dst[(size_t)r * 128 + (jc >> 1)] = packh2(v0 * s, v1 * s);
                dst[(size_t)(r + 8) * 128 + (jc >> 1)] = packh2(v2 * s, v3 * s);
            }
        }
}

// ---------------------------------------------------------------------------
// Persistent ragged flash attention: fp16 mma, half2 ex2 softmax, ones-column
// row sums, 3-stage cp.async K/V ring, one barrier per chunk. (unchanged r8)
// ---------------------------------------------------------------------------
__global__ __launch_bounds__(256, 2) void attn8(const int* __restrict__ lens)
{
    __shared__ __align__(16) uint32_t KV[3][2][64][20];
    __shared__ int s_w;

    const int tid = threadIdx.x, lane = tid & 31, wid = tid >> 5;
    const int g = lane >> 2, tig = lane & 3;
    const int m0 = wid * 16;
    const uint32_t kvbase = (uint32_t)__cvta_generic_to_shared(&KV[0][0][0][0]);
    const uint32_t laneK = (uint32_t)((lane >> 4) * 640 + (lane & 7) * 80 + ((lane >> 3) & 1) * 16);
    const uint32_t laneVt = (uint32_t)(((lane >> 3) & 1) * 640 + (lane & 7) * 80 + (lane >> 4) * 16);
    const int ra = tid >> 2, sa = tid & 3;
    const uint32_t raoff = (uint32_t)(ra * 80 + sa * 16);
    const uint32_t ONE2 = 0x3C003C00u;

    for (;;) {
        if (tid == 0) s_w = atomicAdd(&g_ticket, 1);
        __syncthreads();
        const int w = s_w;
        if (w >= g_nwork) return;
        const int pr = g_pairs[w >> 3], h = w & 7;
        const int b = pr >> 8, qt = pr & 255;
        const int L = lens[b], q0 = qt * 128, off = g_off[b];

        uint32_t qf[2][4];
        {
            size_t rA = (size_t)(off + q0 + m0 + g) * 128;
            size_t rB = rA + 8 * 128;
            #pragma unroll
            for (int ks = 0; ks < 2; ks++) {
                int cb = h * 16 + ks * 8;
                qf[ks][0] = g_q16[rA + cb + tig];
                qf[ks][1] = g_q16[rB + cb + tig];
                qf[ks][2] = g_q16[rA + cb + tig + 4];
                qf[ks][3] = g_q16[rB + cb + tig + 4];
            }
        }

        float o[4][4];
        #pragma unroll
        for (int nt = 0; nt < 4; nt++)
            #pragma unroll
            for (int i = 0; i < 4; i++) o[nt][i] = 0.f;
        float lacc[4] = {0.f, 0.f, 0.f, 0.f};

        const int nch = (L + 63) >> 6;

        const uint32_t* pk = g_k16 + (size_t)(off + ra) * 128 + h * 16 + sa * 4;
        const uint32_t* pv = g_v16 + (size_t)(off + ra) * 128 + h * 16 + sa * 4;

#define ASTAGE(s) do {                                        \
        uint32_t b_ = kvbase + (uint32_t)(s) * 10240u;        \
        cpa16(b_ + raoff, pk);                                \
        cpa16(b_ + 5120 + raoff, pv);                         \
        CP_COMMIT;                                            \
        pk += 8192; pv += 8192;                               \
    } while (0)

        ASTAGE(0);
        if (nch > 1) ASTAGE(1);
        int cur = 0, nxt = 2;

        for (int c = 0; c < nch; c++) {
            if (c + 1 < nch) { CP_WAIT1; } else { CP_WAIT0; }
            __syncthreads();
            if (c + 2 < nch) { ASTAGE(nxt); if (++nxt == 3) nxt = 0; }

            const uint32_t kb = kvbase + (uint32_t)cur * 10240u;
            const uint32_t vb = kb + 5120u;
            if (++cur == 3) cur = 0;
            const int k0 = c * 64;

            float s_[8][4] = {};
            #pragma unroll
            for (int ks = 0; ks < 2; ks++) {
                #pragma unroll
                for (int p = 0; p < 4; p++) {
                    uint32_t kr[4];
                    ldm4(kr, kb + p * 1280 + ks * 32 + laneK);
                    mma_f16(s_[2 * p], qf[ks][0], qf[ks][1], qf[ks][2], qf[ks][3],
                            kr[0], kr[1]);
                    mma_f16(s_[2 * p + 1], qf[ks][0], qf[ks][1], qf[ks][2], qf[ks][3],
                            kr[2], kr[3]);
                }
            }
            if (k0 + 64 > L) {
                #pragma unroll
                for (int jt = 0; jt < 8; jt++) {
                    int col = k0 + jt * 8 + 2 * tig;
                    if (col >= L)     { s_[jt][0] = -1e9f; s_[jt][2] = -1e9f; }
                    if (col + 1 >= L) { s_[jt][1] = -1e9f; s_[jt][3] = -1e9f; }
                }
            }

            #pragma unroll
            for (int t = 0; t < 4; t++) {
                uint32_t a0 = ex2h2(packh2(s_[2 * t][0],     s_[2 * t][1]));
                uint32_t a1 = ex2h2(packh2(s_[2 * t][2],     s_[2 * t][3]));
                uint32_t a2 = ex2h2(packh2(s_[2 * t + 1][0], s_[2 * t + 1][1]));
                uint32_t a3 = ex2h2(packh2(s_[2 * t + 1][2], s_[2 * t + 1][3]));
                uint32_t v0[4], v1[4];
                ldm4t(v0, vb + t * 1280 + laneVt);
                ldm4t(v1, vb + t * 1280 + 32 + laneVt);
                mma_f16(o[0], a0, a1, a2, a3, v0[0], v0[1]);
                mma_f16(o[1], a0, a1, a2, a3, v0[2], v0[3]);
                mma_f16(o[2], a0, a1, a2, a3, v1[0], v1[1]);
                mma_f16(o[3], a0, a1, a2, a3, v1[2], v1[3]);
                mma_f16(lacc, a0, a1, a2, a3, ONE2, ONE2);
            }
        }
#undef ASTAGE

        float i0 = 1.f / lacc[0], i1 = 1.f / lacc[2];

        int qa = q0 + m0 + g, qb = qa + 8;
        #pragma unroll
        for (int nt = 0; nt < 4; nt++) {
            int ci = h * 16 + nt * 4 + tig;
            if (qa < L)
                g_a16[(size_t)(off + qa) * 128 + ci] = packh2(o[nt][0] * i0, o[nt][1] * i0);
            if (qb < L)
                g_a16[(size_t)(off + qb) * 128 + ci] = packh2(o[nt][2] * i1, o[nt][3] * i1);
        }
    }
}

// ---------------------------------------------------------------------------
extern "C" void kernel_launch(void* const* d_in, const int* in_sizes, int n_in,
                              void* d_out, int out_size)
{
    const float* x      = (const float*)d_in[0];
    const int*   lens   = (const int*)d_in[2];
    const float* qkv_w  = (const float*)d_in[3];
    const float* qkv_b  = (const float*)d_in[4];
    const float* proj_w = (const float*)d_in[5];
    const float* proj_b = (const float*)d_in[6];
    float* out = (float*)d_out;

    __half *x16p, *a16p, *wq, *wp;
    cudaGetSymbolAddress((void**)&x16p, g_x16);
    cudaGetSymbolAddress((void**)&a16p, g_a16);
    cudaGetSymbolAddress((void**)&wq,   g_wq16);
    cudaGetSymbolAddress((void**)&wp,   g_wp16);

    cudaFuncSetAttribute(gemm9, cudaFuncAttributeMaxDynamicSharedMemorySize, 30720);

    prep<<<1872, 256>>>((const float4*)x, lens, qkv_w, proj_w);
    gemm9<<<dim3(12, 101), 128, 30720>>>(x16p, wq, qkv_b, nullptr, 1);
    attn8<<<NPERS, 256>>>(lens);
    gemm9<<<dim3(4, 101), 128, 30720>>>(a16p, wp, proj_b, out, 0);
}